// round 1
// baseline (speedup 1.0000x reference)
#include <cuda_runtime.h>

#define Nn 100000
#define Ee 400000
#define Dd 300
#define Gg 128
#define EPSv 1e-5f

// ---------------- scratch (device globals; allocated at module load) ----------
__device__ float g_x   [(size_t)Nn * Dd];   // node embedding sums
__device__ float g_ea  [(size_t)Ee * Dd];   // edge attr sums; reused as node-MLP1 hidden
__device__ float g_h   [(size_t)Ee * Dd];   // edge-MLP hidden; reused as node-MLP2 hidden
__device__ float g_m   [(size_t)Ee * Dd];   // node-MLP1 output (messages)
__device__ float g_agg [(size_t)Nn * Dd];   // scatter-mean aggregate
__device__ float g_xenc[(size_t)Nn * Dd];   // node-MLP2 output
__device__ float g_cnt [Nn];
__device__ float g_sign[Ee];
__device__ float g_gsum[Gg], g_gsq[Gg], g_gcnt[Gg], g_gmean[Gg], g_grstd[Gg];

// ---------------- zero scratch that is accumulated into -----------------------
__global__ void k_zero() {
    long long i = (long long)blockIdx.x * blockDim.x + threadIdx.x;
    long long stride = (long long)gridDim.x * blockDim.x;
    for (long long j = i; j < (long long)Nn * Dd; j += stride) g_agg[j] = 0.f;
    for (long long j = i; j < Nn; j += stride) g_cnt[j] = 0.f;
    if (i < Gg) { g_gsum[i] = 0.f; g_gsq[i] = 0.f; g_gcnt[i] = 0.f; }
}

__global__ void k_sign_init() {
    int i = blockIdx.x * blockDim.x + threadIdx.x;
    if (i < Ee) g_sign[i] = 1.f;
}
__global__ void k_sign_set(const int* __restrict__ ase) {
    int i = blockIdx.x * blockDim.x + threadIdx.x;
    if (i < Ee / 2) g_sign[ase[i]] = -1.f;
}

// ---------------- embedding gather-sums (T=4 -> int4 token load) --------------
__global__ void k_embed_x(const int* __restrict__ tok, const float* __restrict__ emb) {
    int i = blockIdx.x * blockDim.x + threadIdx.x;
    if (i >= Nn * Dd) return;
    int n = i / Dd, d = i - n * Dd;
    int4 t = ((const int4*)tok)[n];
    g_x[i] = emb[(size_t)t.x * Dd + d] + emb[(size_t)t.y * Dd + d] +
             emb[(size_t)t.z * Dd + d] + emb[(size_t)t.w * Dd + d];
}

__global__ void k_embed_ea(const int* __restrict__ tok, const float* __restrict__ emb) {
    int i = blockIdx.x * blockDim.x + threadIdx.x;
    if (i >= Ee * Dd) return;
    int e = i / Dd, d = i - e * Dd;
    int4 t = ((const int4*)tok)[e];
    float s = emb[(size_t)t.x * Dd + d] + emb[(size_t)t.y * Dd + d] +
              emb[(size_t)t.z * Dd + d] + emb[(size_t)t.w * Dd + d];
    g_ea[i] = s * g_sign[e];
}

// ---------------- fused gather-GEMM: out = act(cat(segs) @ W + b) -------------
// A row m = concat of up to 3 segments of width 300 each, each segment a row
// gathered from src via idx (idx==nullptr -> identity). BK=20 divides 300, so a
// K-chunk never straddles a segment boundary.
__global__ __launch_bounds__(256) void k_gemm(
    int M, int K,
    const float* __restrict__ s0, const int* __restrict__ i0,
    const float* __restrict__ s1, const int* __restrict__ i1,
    const float* __restrict__ s2, const int* __restrict__ i2,
    const float* __restrict__ W, const float* __restrict__ bias,
    float* __restrict__ out, int relu)
{
    __shared__ float As[64][21];            // [m][kk], padded
    __shared__ float Bs[20][64];            // [kk][n]
    __shared__ const float* rp[3][64];      // per-row base pointers per segment

    const int tid = threadIdx.x;
    const int tile_m = blockIdx.x * 64;
    const int tile_n = blockIdx.y * 64;
    const int nseg = K / 300;

    if (tid < nseg * 64) {
        int seg = tid >> 6, m = tid & 63;
        int gm = tile_m + m; if (gm >= M) gm = M - 1;   // clamp: safe reads, store guarded
        const float* s; const int* ix;
        if (seg == 0)      { s = s0; ix = i0; }
        else if (seg == 1) { s = s1; ix = i1; }
        else               { s = s2; ix = i2; }
        int r = ix ? ix[gm] : gm;
        rp[seg][m] = s + (size_t)r * Dd;
    }
    __syncthreads();

    const int ty = tid >> 4, tx = tid & 15;
    float acc[4][4];
#pragma unroll
    for (int a = 0; a < 4; a++)
#pragma unroll
        for (int b = 0; b < 4; b++) acc[a][b] = 0.f;

    for (int k0 = 0; k0 < K; k0 += 20) {
        int seg = k0 / 300;
        int koff = k0 - seg * 300;
        // A tile: each thread reads a contiguous run of k within one row
#pragma unroll
        for (int t = 0; t < 5; t++) {
            int i = tid + t * 256;
            int m = i / 20, kk = i - m * 20;
            As[m][kk] = rp[seg][m][koff + kk];
        }
        // B tile: coalesced rows of W
#pragma unroll
        for (int t = 0; t < 5; t++) {
            int i = tid + t * 256;
            int kk = i >> 6, n = i & 63;
            int gn = tile_n + n;
            Bs[kk][n] = (gn < Dd) ? W[(size_t)(k0 + kk) * Dd + gn] : 0.f;
        }
        __syncthreads();
#pragma unroll
        for (int kk = 0; kk < 20; kk++) {
            float a0 = As[ty * 4 + 0][kk];
            float a1 = As[ty * 4 + 1][kk];
            float a2 = As[ty * 4 + 2][kk];
            float a3 = As[ty * 4 + 3][kk];
            float4 b = *(const float4*)&Bs[kk][tx * 4];
            acc[0][0] += a0 * b.x; acc[0][1] += a0 * b.y; acc[0][2] += a0 * b.z; acc[0][3] += a0 * b.w;
            acc[1][0] += a1 * b.x; acc[1][1] += a1 * b.y; acc[1][2] += a1 * b.z; acc[1][3] += a1 * b.w;
            acc[2][0] += a2 * b.x; acc[2][1] += a2 * b.y; acc[2][2] += a2 * b.z; acc[2][3] += a2 * b.w;
            acc[3][0] += a3 * b.x; acc[3][1] += a3 * b.y; acc[3][2] += a3 * b.z; acc[3][3] += a3 * b.w;
        }
        __syncthreads();
    }

#pragma unroll
    for (int ii = 0; ii < 4; ii++) {
        int gm = tile_m + ty * 4 + ii;
        if (gm >= M) continue;
#pragma unroll
        for (int jj = 0; jj < 4; jj++) {
            int gn = tile_n + tx * 4 + jj;
            if (gn >= Dd) continue;
            float v = acc[ii][jj] + __ldg(&bias[gn]);
            if (relu) v = fmaxf(v, 0.f);
            out[(size_t)gm * Dd + gn] = v;
        }
    }
}

// ---------------- scatter-mean ------------------------------------------------
__global__ void k_cnt(const int* __restrict__ col) {
    int e = blockIdx.x * blockDim.x + threadIdx.x;
    if (e < Ee) atomicAdd(&g_cnt[col[e]], 1.f);
}
__global__ void k_scatter(const int* __restrict__ col) {
    int i = blockIdx.x * blockDim.x + threadIdx.x;
    if (i >= Ee * Dd) return;
    int e = i / Dd, d = i - e * Dd;
    atomicAdd(&g_agg[(size_t)col[e] * Dd + d], g_m[i]);
}
__global__ void k_aggnorm() {
    int i = blockIdx.x * blockDim.x + threadIdx.x;
    if (i >= Nn * Dd) return;
    g_agg[i] *= 1.f / fmaxf(g_cnt[i / Dd], 1.f);
}

// ---------------- graph layer norm -------------------------------------------
__global__ void k_stats(const int* __restrict__ batch) {
    int n = blockIdx.x;
    float s = 0.f, q = 0.f;
    for (int d = threadIdx.x; d < Dd; d += 128) {
        float v = g_xenc[(size_t)n * Dd + d];
        s += v; q += v * v;
    }
#pragma unroll
    for (int o = 16; o; o >>= 1) {
        s += __shfl_down_sync(0xFFFFFFFFu, s, o);
        q += __shfl_down_sync(0xFFFFFFFFu, q, o);
    }
    __shared__ float ss[4], qq[4];
    int w = threadIdx.x >> 5, l = threadIdx.x & 31;
    if (l == 0) { ss[w] = s; qq[w] = q; }
    __syncthreads();
    if (threadIdx.x == 0) {
        s = ss[0] + ss[1] + ss[2] + ss[3];
        q = qq[0] + qq[1] + qq[2] + qq[3];
        int g = batch[n];
        atomicAdd(&g_gsum[g], s);
        atomicAdd(&g_gsq[g], q);
        atomicAdd(&g_gcnt[g], 1.f);
    }
}
__global__ void k_finalize() {
    int g = threadIdx.x;
    if (g < Gg) {
        float denom = fmaxf(g_gcnt[g] * (float)Dd, 1.f);
        float mean = g_gsum[g] / denom;
        float var = g_gsq[g] / denom - mean * mean;
        g_gmean[g] = mean;
        g_grstd[g] = rsqrtf(var + EPSv);
    }
}
__global__ void k_apply(const int* __restrict__ batch,
                        const float* __restrict__ lnw, const float* __restrict__ lnb,
                        float* __restrict__ out) {
    int i = blockIdx.x * blockDim.x + threadIdx.x;
    if (i >= Nn * Dd) return;
    int n = i / Dd, d = i - n * Dd;
    int g = batch[n];
    out[i] = (g_xenc[i] - g_gmean[g]) * g_grstd[g] * lnw[d] + lnb[d];
}

// ---------------- launch ------------------------------------------------------
static float* symf(const void* s) {
    void* p = nullptr;
    cudaGetSymbolAddress(&p, s);
    return (float*)p;
}

extern "C" void kernel_launch(void* const* d_in, const int* in_sizes, int n_in,
                              void* d_out, int out_size) {
    const int*   x_tok  = (const int*)d_in[0];
    const int*   ea_tok = (const int*)d_in[1];
    const int*   eidx   = (const int*)d_in[2];   // [2,E]: row = eidx, col = eidx+E
    const int*   ase    = (const int*)d_in[3];
    const int*   batch  = (const int*)d_in[4];
    const float* emb    = (const float*)d_in[5];
    const float* ew1  = (const float*)d_in[6];
    const float* eb1  = (const float*)d_in[7];
    const float* ew2  = (const float*)d_in[8];
    const float* eb2  = (const float*)d_in[9];
    const float* n1w1 = (const float*)d_in[10];
    const float* n1b1 = (const float*)d_in[11];
    const float* n1w2 = (const float*)d_in[12];
    const float* n1b2 = (const float*)d_in[13];
    const float* n2w1 = (const float*)d_in[14];
    const float* n2b1 = (const float*)d_in[15];
    const float* n2w2 = (const float*)d_in[16];
    const float* n2b2 = (const float*)d_in[17];
    const float* lnw  = (const float*)d_in[18];
    const float* lnb  = (const float*)d_in[19];

    const int* row = eidx;
    const int* col = eidx + Ee;

    float* out = (float*)d_out;
    float* edge_out = out + (size_t)Nn * Dd;   // [x_out | edge_enc]

    float* px    = symf(g_x);
    float* pea   = symf(g_ea);
    float* ph    = symf(g_h);
    float* pm    = symf(g_m);
    float* pagg  = symf(g_agg);
    float* pxenc = symf(g_xenc);

    const int T256 = 256;
    k_zero<<<2048, T256>>>();
    k_sign_init<<<(Ee + T256 - 1) / T256, T256>>>();
    k_sign_set<<<(Ee / 2 + T256 - 1) / T256, T256>>>(ase);
    k_embed_x<<<(Nn * Dd + T256 - 1) / T256, T256>>>(x_tok, emb);
    k_embed_ea<<<(Ee * Dd + T256 - 1) / T256, T256>>>(ea_tok, emb);

    dim3 gE((Ee + 63) / 64, 5), gN((Nn + 63) / 64, 5);
    // edge MLP
    k_gemm<<<gE, T256>>>(Ee, 900, px, row, px, col, pea, nullptr, ew1, eb1, ph, 1);
    k_gemm<<<gE, T256>>>(Ee, 300, ph, nullptr, nullptr, nullptr, nullptr, nullptr, ew2, eb2, edge_out, 0);
    // node MLP1 (messages)
    k_gemm<<<gE, T256>>>(Ee, 600, px, row, edge_out, nullptr, nullptr, nullptr, n1w1, n1b1, pea, 1);
    k_gemm<<<gE, T256>>>(Ee, 300, pea, nullptr, nullptr, nullptr, nullptr, nullptr, n1w2, n1b2, pm, 0);
    // scatter mean
    k_cnt<<<(Ee + T256 - 1) / T256, T256>>>(col);
    k_scatter<<<(Ee * Dd + T256 - 1) / T256, T256>>>(col);
    k_aggnorm<<<(Nn * Dd + T256 - 1) / T256, T256>>>();
    // node MLP2
    k_gemm<<<gN, T256>>>(Nn, 600, px, nullptr, pagg, nullptr, nullptr, nullptr, n2w1, n2b1, ph, 1);
    k_gemm<<<gN, T256>>>(Nn, 300, ph, nullptr, nullptr, nullptr, nullptr, nullptr, n2w2, n2b2, pxenc, 0);
    // graph layer norm
    k_stats<<<Nn, 128>>>(batch);
    k_finalize<<<1, 128>>>();
    k_apply<<<(Nn * Dd + T256 - 1) / T256, T256>>>(batch, lnw, lnb, out);
}

// round 2
// speedup vs baseline: 2.5039x; 2.5039x over previous
#include <cuda_runtime.h>

#define Nn 100000
#define Ee 400000
#define Dd 300
#define Gg 128
#define EPSv 1e-5f

// ---------------- scratch (device globals; allocated at module load) ----------
__device__ __align__(16) float g_x   [(size_t)Nn * Dd];
__device__ __align__(16) float g_ea  [(size_t)Ee * Dd];
__device__ __align__(16) float g_h   [(size_t)Ee * Dd];
__device__ __align__(16) float g_m   [(size_t)Ee * Dd];
__device__ __align__(16) float g_agg [(size_t)Nn * Dd];
__device__ __align__(16) float g_xenc[(size_t)Nn * Dd];
__device__ float g_cnt [Nn];
__device__ float g_sign[Ee];
__device__ float g_gsum[Gg], g_gsq[Gg], g_gcnt[Gg], g_gmean[Gg], g_grstd[Gg];

// ---------------- zero scratch that is accumulated into -----------------------
__global__ void k_zero() {
    long long i = (long long)blockIdx.x * blockDim.x + threadIdx.x;
    long long stride = (long long)gridDim.x * blockDim.x;
    for (long long j = i; j < (long long)Nn * Dd; j += stride) g_agg[j] = 0.f;
    for (long long j = i; j < Nn; j += stride) g_cnt[j] = 0.f;
    if (i < Gg) { g_gsum[i] = 0.f; g_gsq[i] = 0.f; g_gcnt[i] = 0.f; }
}

__global__ void k_sign_init() {
    int i = blockIdx.x * blockDim.x + threadIdx.x;
    if (i < Ee) g_sign[i] = 1.f;
}
__global__ void k_sign_set(const int* __restrict__ ase) {
    int i = blockIdx.x * blockDim.x + threadIdx.x;
    if (i < Ee / 2) g_sign[ase[i]] = -1.f;
}

// ---------------- embedding gather-sums (T=4 -> int4 token load) --------------
__global__ void k_embed_x(const int* __restrict__ tok, const float* __restrict__ emb) {
    int i = blockIdx.x * blockDim.x + threadIdx.x;
    if (i >= Nn * Dd) return;
    int n = i / Dd, d = i - n * Dd;
    int4 t = ((const int4*)tok)[n];
    g_x[i] = emb[(size_t)t.x * Dd + d] + emb[(size_t)t.y * Dd + d] +
             emb[(size_t)t.z * Dd + d] + emb[(size_t)t.w * Dd + d];
}

__global__ void k_embed_ea(const int* __restrict__ tok, const float* __restrict__ emb) {
    int i = blockIdx.x * blockDim.x + threadIdx.x;
    if (i >= Ee * Dd) return;
    int e = i / Dd, d = i - e * Dd;
    int4 t = ((const int4*)tok)[e];
    float s = emb[(size_t)t.x * Dd + d] + emb[(size_t)t.y * Dd + d] +
              emb[(size_t)t.z * Dd + d] + emb[(size_t)t.w * Dd + d];
    g_ea[i] = s * g_sign[e];
}

// ---------------- tf32 helpers ------------------------------------------------
__device__ __forceinline__ unsigned f2tf(float f) {
    unsigned u;
    asm("cvt.rna.tf32.f32 %0, %1;" : "=r"(u) : "f"(f));
    return u;
}
__device__ __forceinline__ void mma_tf32(float* c, unsigned a0, unsigned a1,
                                         unsigned a2, unsigned a3,
                                         unsigned b0, unsigned b1) {
    asm volatile(
        "mma.sync.aligned.m16n8k8.row.col.f32.tf32.tf32.f32 "
        "{%0,%1,%2,%3}, {%4,%5,%6,%7}, {%8,%9}, {%0,%1,%2,%3};"
        : "+f"(c[0]), "+f"(c[1]), "+f"(c[2]), "+f"(c[3])
        : "r"(a0), "r"(a1), "r"(a2), "r"(a3), "r"(b0), "r"(b1));
}

// ---------------- fused gather-GEMM on tensor cores ---------------------------
// out[M,300] = act( cat(segs)[M,K] @ W[K,300] + b ), K = nseg*300.
// A rows gathered via per-segment row-pointer table. BM=64, BN=64, BK=32;
// each 300-wide segment iterates 10 chunks (last is 12 wide, zero-padded).
#define AS_STRIDE 36
#define BS_STRIDE 72
__global__ __launch_bounds__(256) void k_gemm_tc(
    int M, int nseg,
    const float* __restrict__ s0, const int* __restrict__ i0,
    const float* __restrict__ s1, const int* __restrict__ i1,
    const float* __restrict__ s2, const int* __restrict__ i2,
    const float* __restrict__ W, const float* __restrict__ bias,
    float* __restrict__ out, int relu)
{
    __shared__ unsigned As[64 * AS_STRIDE];      // [m][kk]
    __shared__ unsigned Bs[32 * BS_STRIDE];      // [kk][n]
    __shared__ const float* rp[3][64];

    const int tid = threadIdx.x;
    const int lane = tid & 31;
    const int grp = lane >> 2;            // 0..7
    const int tig = lane & 3;             // 0..3
    const int w = tid >> 5;
    const int wm = (w & 3) * 16;          // warp M offset
    const int wn = (w >> 2) * 32;         // warp N offset
    const int tile_m = blockIdx.x * 64;
    const int tile_n = blockIdx.y * 64;

    if (tid < nseg * 64) {
        int seg = tid >> 6, m = tid & 63;
        int gm = tile_m + m; if (gm >= M) gm = M - 1;
        const float* s; const int* ix;
        if (seg == 0)      { s = s0; ix = i0; }
        else if (seg == 1) { s = s1; ix = i1; }
        else               { s = s2; ix = i2; }
        int r = ix ? ix[gm] : gm;
        rp[seg][m] = s + (size_t)r * Dd;
    }
    __syncthreads();

    float acc[4][4];
#pragma unroll
    for (int a = 0; a < 4; a++)
#pragma unroll
        for (int b = 0; b < 4; b++) acc[a][b] = 0.f;

    for (int seg = 0; seg < nseg; ++seg) {
        for (int koff = 0; koff < 300; koff += 32) {
            const int width = (300 - koff) < 32 ? (300 - koff) : 32;  // 32 or 12

            // ---- A tile: 64x32, float4 per thread slot, 2 iters ----
#pragma unroll
            for (int it = 0; it < 2; ++it) {
                int s = tid + it * 256;            // 0..511
                int m = s >> 3, g = (s & 7) << 2;  // kk group of 4
                float4 v = make_float4(0.f, 0.f, 0.f, 0.f);
                if (g < width) v = *(const float4*)(rp[seg][m] + koff + g);
                unsigned* dst = &As[m * AS_STRIDE + g];
                dst[0] = f2tf(v.x); dst[1] = f2tf(v.y);
                dst[2] = f2tf(v.z); dst[3] = f2tf(v.w);
            }
            // ---- B tile: 32x64 ----
#pragma unroll
            for (int it = 0; it < 2; ++it) {
                int s = tid + it * 256;
                int kk = s >> 4, n4 = (s & 15) << 2;
                float4 v = make_float4(0.f, 0.f, 0.f, 0.f);
                if (kk < width && (tile_n + n4) < Dd)
                    v = *(const float4*)&W[(size_t)(seg * 300 + koff + kk) * Dd + tile_n + n4];
                unsigned* dst = &Bs[kk * BS_STRIDE + n4];
                dst[0] = f2tf(v.x); dst[1] = f2tf(v.y);
                dst[2] = f2tf(v.z); dst[3] = f2tf(v.w);
            }
            __syncthreads();

#pragma unroll
            for (int ks = 0; ks < 4; ++ks) {
                if (ks * 8 >= width) break;        // skip all-zero k-steps (uniform)
                const int k0 = ks * 8;
                unsigned a0 = As[(wm + grp)     * AS_STRIDE + k0 + tig];
                unsigned a1 = As[(wm + grp + 8) * AS_STRIDE + k0 + tig];
                unsigned a2 = As[(wm + grp)     * AS_STRIDE + k0 + tig + 4];
                unsigned a3 = As[(wm + grp + 8) * AS_STRIDE + k0 + tig + 4];
#pragma unroll
                for (int nt = 0; nt < 4; ++nt) {
                    unsigned b0 = Bs[(k0 + tig)     * BS_STRIDE + wn + nt * 8 + grp];
                    unsigned b1 = Bs[(k0 + tig + 4) * BS_STRIDE + wn + nt * 8 + grp];
                    mma_tf32(acc[nt], a0, a1, a2, a3, b0, b1);
                }
            }
            __syncthreads();
        }
    }

    // ---- epilogue: c0 (r,2t) c1 (r,2t+1) c2 (r+8,2t) c3 (r+8,2t+1) ----
#pragma unroll
    for (int nt = 0; nt < 4; ++nt) {
        int gn0 = tile_n + wn + nt * 8 + tig * 2;
#pragma unroll
        for (int half = 0; half < 2; ++half) {
            int gm = tile_m + wm + grp + half * 8;
            if (gm >= M) continue;
#pragma unroll
            for (int cc = 0; cc < 2; ++cc) {
                int gn = gn0 + cc;
                if (gn >= Dd) continue;
                float v = acc[nt][half * 2 + cc] + __ldg(&bias[gn]);
                if (relu) v = fmaxf(v, 0.f);
                out[(size_t)gm * Dd + gn] = v;
            }
        }
    }
}

// ---------------- scatter-mean ------------------------------------------------
__global__ void k_cnt(const int* __restrict__ col) {
    int e = blockIdx.x * blockDim.x + threadIdx.x;
    if (e < Ee) atomicAdd(&g_cnt[col[e]], 1.f);
}
__global__ void k_scatter(const int* __restrict__ col) {
    int i = blockIdx.x * blockDim.x + threadIdx.x;
    if (i >= Ee * Dd) return;
    int e = i / Dd, d = i - e * Dd;
    atomicAdd(&g_agg[(size_t)col[e] * Dd + d], g_m[i]);
}
__global__ void k_aggnorm() {
    int i = blockIdx.x * blockDim.x + threadIdx.x;
    if (i >= Nn * Dd) return;
    g_agg[i] *= 1.f / fmaxf(g_cnt[i / Dd], 1.f);
}

// ---------------- graph layer norm -------------------------------------------
__global__ void k_stats(const int* __restrict__ batch) {
    int n = blockIdx.x;
    float s = 0.f, q = 0.f;
    for (int d = threadIdx.x; d < Dd; d += 128) {
        float v = g_xenc[(size_t)n * Dd + d];
        s += v; q += v * v;
    }
#pragma unroll
    for (int o = 16; o; o >>= 1) {
        s += __shfl_down_sync(0xFFFFFFFFu, s, o);
        q += __shfl_down_sync(0xFFFFFFFFu, q, o);
    }
    __shared__ float ss[4], qq[4];
    int w = threadIdx.x >> 5, l = threadIdx.x & 31;
    if (l == 0) { ss[w] = s; qq[w] = q; }
    __syncthreads();
    if (threadIdx.x == 0) {
        s = ss[0] + ss[1] + ss[2] + ss[3];
        q = qq[0] + qq[1] + qq[2] + qq[3];
        int g = batch[n];
        atomicAdd(&g_gsum[g], s);
        atomicAdd(&g_gsq[g], q);
        atomicAdd(&g_gcnt[g], 1.f);
    }
}
__global__ void k_finalize() {
    int g = threadIdx.x;
    if (g < Gg) {
        float denom = fmaxf(g_gcnt[g] * (float)Dd, 1.f);
        float mean = g_gsum[g] / denom;
        float var = g_gsq[g] / denom - mean * mean;
        g_gmean[g] = mean;
        g_grstd[g] = rsqrtf(var + EPSv);
    }
}
__global__ void k_apply(const int* __restrict__ batch,
                        const float* __restrict__ lnw, const float* __restrict__ lnb,
                        float* __restrict__ out) {
    int i = blockIdx.x * blockDim.x + threadIdx.x;
    if (i >= Nn * Dd) return;
    int n = i / Dd, d = i - n * Dd;
    int g = batch[n];
    out[i] = (g_xenc[i] - g_gmean[g]) * g_grstd[g] * lnw[d] + lnb[d];
}

// ---------------- launch ------------------------------------------------------
static float* symf(const void* s) {
    void* p = nullptr;
    cudaGetSymbolAddress(&p, s);
    return (float*)p;
}

extern "C" void kernel_launch(void* const* d_in, const int* in_sizes, int n_in,
                              void* d_out, int out_size) {
    const int*   x_tok  = (const int*)d_in[0];
    const int*   ea_tok = (const int*)d_in[1];
    const int*   eidx   = (const int*)d_in[2];
    const int*   ase    = (const int*)d_in[3];
    const int*   batch  = (const int*)d_in[4];
    const float* emb    = (const float*)d_in[5];
    const float* ew1  = (const float*)d_in[6];
    const float* eb1  = (const float*)d_in[7];
    const float* ew2  = (const float*)d_in[8];
    const float* eb2  = (const float*)d_in[9];
    const float* n1w1 = (const float*)d_in[10];
    const float* n1b1 = (const float*)d_in[11];
    const float* n1w2 = (const float*)d_in[12];
    const float* n1b2 = (const float*)d_in[13];
    const float* n2w1 = (const float*)d_in[14];
    const float* n2b1 = (const float*)d_in[15];
    const float* n2w2 = (const float*)d_in[16];
    const float* n2b2 = (const float*)d_in[17];
    const float* lnw  = (const float*)d_in[18];
    const float* lnb  = (const float*)d_in[19];

    const int* row = eidx;
    const int* col = eidx + Ee;

    float* out = (float*)d_out;
    float* edge_out = out + (size_t)Nn * Dd;

    float* px    = symf(g_x);
    float* pea   = symf(g_ea);
    float* ph    = symf(g_h);
    float* pm    = symf(g_m);
    float* pagg  = symf(g_agg);
    float* pxenc = symf(g_xenc);

    const int T256 = 256;
    k_zero<<<2048, T256>>>();
    k_sign_init<<<(Ee + T256 - 1) / T256, T256>>>();
    k_sign_set<<<(Ee / 2 + T256 - 1) / T256, T256>>>(ase);
    k_embed_x<<<(Nn * Dd + T256 - 1) / T256, T256>>>(x_tok, emb);
    k_embed_ea<<<(Ee * Dd + T256 - 1) / T256, T256>>>(ea_tok, emb);

    dim3 gE((Ee + 63) / 64, 5), gN((Nn + 63) / 64, 5);
    // edge MLP
    k_gemm_tc<<<gE, T256>>>(Ee, 3, px, row, px, col, pea, nullptr, ew1, eb1, ph, 1);
    k_gemm_tc<<<gE, T256>>>(Ee, 1, ph, nullptr, nullptr, nullptr, nullptr, nullptr, ew2, eb2, edge_out, 0);
    // node MLP1 (messages)
    k_gemm_tc<<<gE, T256>>>(Ee, 2, px, row, edge_out, nullptr, nullptr, nullptr, n1w1, n1b1, pea, 1);
    k_gemm_tc<<<gE, T256>>>(Ee, 1, pea, nullptr, nullptr, nullptr, nullptr, nullptr, n1w2, n1b2, pm, 0);
    // scatter mean
    k_cnt<<<(Ee + T256 - 1) / T256, T256>>>(col);
    k_scatter<<<(Ee * Dd + T256 - 1) / T256, T256>>>(col);
    k_aggnorm<<<(Nn * Dd + T256 - 1) / T256, T256>>>();
    // node MLP2
    k_gemm_tc<<<gN, T256>>>(Nn, 2, px, nullptr, pagg, nullptr, nullptr, nullptr, n2w1, n2b1, ph, 1);
    k_gemm_tc<<<gN, T256>>>(Nn, 1, ph, nullptr, nullptr, nullptr, nullptr, nullptr, n2w2, n2b2, pxenc, 0);
    // graph layer norm
    k_stats<<<Nn, 128>>>(batch);
    k_finalize<<<1, 128>>>();
    k_apply<<<(Nn * Dd + T256 - 1) / T256, T256>>>(batch, lnw, lnb, out);
}

// round 3
// speedup vs baseline: 4.5427x; 1.8142x over previous
#include <cuda_runtime.h>

#define Nn 100000
#define Ee 400000
#define Dd 300
#define Vv 3000
#define Gg 128
#define EPSv 1e-5f

// ---------------- scratch (device globals) ------------------------------------
__device__ __align__(16) float g_embA[(size_t)Vv * Dd];
__device__ __align__(16) float g_embB[(size_t)Vv * Dd];
__device__ __align__(16) float g_embC[(size_t)Vv * Dd];
__device__ __align__(16) float g_embD[(size_t)Vv * Dd];
__device__ __align__(16) float g_embF[(size_t)Vv * Dd];
__device__ __align__(16) float g_gsA [(size_t)Nn * Dd];
__device__ __align__(16) float g_gsB [(size_t)Nn * Dd];
__device__ __align__(16) float g_gsD [(size_t)Nn * Dd];
__device__ __align__(16) float g_gsF [(size_t)Nn * Dd];
__device__ __align__(16) float g_h   [(size_t)Ee * Dd];   // h1, later node2 hidden
__device__ __align__(16) float g_m   [(size_t)Ee * Dd];   // node1 hidden
__device__ __align__(16) float g_agg [(size_t)Nn * Dd];
__device__ __align__(16) float g_xenc[(size_t)Nn * Dd];
__device__ __align__(16) float g_w2p [Dd * Dd];           // ew2 @ We
__device__ __align__(16) float g_wcat[Dd * 2 * Dd];       // [300][600] = [ew2 | w2p]
__device__ float g_bcat[2 * Dd];
__device__ float g_b2[Dd];
__device__ float g_cnt[Nn];
__device__ float g_sign[Ee];
__device__ float g_gsum[Gg], g_gsq[Gg], g_gcnt[Gg], g_gmean[Gg], g_grstd[Gg];

// ---------------- init kernels -------------------------------------------------
__global__ void k_zero() {
    long long i = (long long)blockIdx.x * blockDim.x + threadIdx.x;
    long long stride = (long long)gridDim.x * blockDim.x;
    for (long long j = i; j < (long long)Nn * Dd; j += stride) g_agg[j] = 0.f;
    for (long long j = i; j < Nn; j += stride) g_cnt[j] = 0.f;
    if (i < Gg) { g_gsum[i] = 0.f; g_gsq[i] = 0.f; g_gcnt[i] = 0.f; }
}
__global__ void k_sign_init() {
    int i = blockIdx.x * blockDim.x + threadIdx.x;
    if (i < Ee) g_sign[i] = 1.f;
}
__global__ void k_sign_set(const int* __restrict__ ase) {
    int i = blockIdx.x * blockDim.x + threadIdx.x;
    if (i < Ee / 2) g_sign[ase[i]] = -1.f;
}

// ---------------- tf32 helpers -------------------------------------------------
__device__ __forceinline__ unsigned f2tf(float f) {
    unsigned u;
    asm("cvt.rna.tf32.f32 %0, %1;" : "=r"(u) : "f"(f));
    return u;
}
__device__ __forceinline__ void mma_tf32(float* c, unsigned a0, unsigned a1,
                                         unsigned a2, unsigned a3,
                                         unsigned b0, unsigned b1) {
    asm volatile(
        "mma.sync.aligned.m16n8k8.row.col.f32.tf32.tf32.f32 "
        "{%0,%1,%2,%3}, {%4,%5,%6,%7}, {%8,%9}, {%0,%1,%2,%3};"
        : "+f"(c[0]), "+f"(c[1]), "+f"(c[2]), "+f"(c[3])
        : "r"(a0), "r"(a1), "r"(a2), "r"(a3), "r"(b0), "r"(b1));
}

// ---------------- generic tensor-core GEMM, K=300 fixed ------------------------
// out = epilogue( A[aidx[m]] @ W + bias ),  W row-major [300, Nout] stride ldw.
// mode 0: plain store to out0 (Nout<=300)
// mode 1: out0 = relu(v + add_src[(add_idx?add_idx[m]:m)*300+n])
// mode 2: atomicAdd(out0[scat_idx[m]*300+n], v)
// mode 3: dual (Nout=600): n<300 -> out0 plain; n>=300 -> out1[n-300] =
//         relu(v + add_src[add_idx[m]*300 + n-300])
#define AS_STRIDE 36
#define BS_STRIDE 72
__global__ __launch_bounds__(256) void k_gemm_tc(
    int M, int Nout,
    const float* __restrict__ A, const int* __restrict__ aidx,
    const float* __restrict__ W, int ldw,
    const float* __restrict__ bias,
    float* __restrict__ out0, float* __restrict__ out1,
    const float* __restrict__ add_src, const int* __restrict__ add_idx,
    const int* __restrict__ scat_idx, int mode)
{
    __shared__ unsigned As[64 * AS_STRIDE];
    __shared__ unsigned Bs[32 * BS_STRIDE];
    __shared__ const float* rp[64];

    const int tid = threadIdx.x;
    const int lane = tid & 31;
    const int grp = lane >> 2;
    const int tig = lane & 3;
    const int w = tid >> 5;
    const int wm = (w & 3) * 16;
    const int wn = (w >> 2) * 32;
    const int tile_m = blockIdx.x * 64;
    const int tile_n = blockIdx.y * 64;

    if (tid < 64) {
        int gm = tile_m + tid; if (gm >= M) gm = M - 1;
        int r = aidx ? aidx[gm] : gm;
        rp[tid] = A + (size_t)r * Dd;
    }
    __syncthreads();

    float acc[4][4];
#pragma unroll
    for (int a = 0; a < 4; a++)
#pragma unroll
        for (int b = 0; b < 4; b++) acc[a][b] = 0.f;

    for (int koff = 0; koff < 300; koff += 32) {
        const int width = (300 - koff) < 32 ? (300 - koff) : 32;  // 32 or 12
#pragma unroll
        for (int it = 0; it < 2; ++it) {
            int s = tid + it * 256;
            int m = s >> 3, g = (s & 7) << 2;
            float4 v = make_float4(0.f, 0.f, 0.f, 0.f);
            if (g < width) v = *(const float4*)(rp[m] + koff + g);
            unsigned* dst = &As[m * AS_STRIDE + g];
            dst[0] = f2tf(v.x); dst[1] = f2tf(v.y);
            dst[2] = f2tf(v.z); dst[3] = f2tf(v.w);
        }
#pragma unroll
        for (int it = 0; it < 2; ++it) {
            int s = tid + it * 256;
            int kk = s >> 4, n4 = (s & 15) << 2;
            float4 v = make_float4(0.f, 0.f, 0.f, 0.f);
            if (kk < width && (tile_n + n4) < Nout)
                v = *(const float4*)&W[(size_t)(koff + kk) * ldw + tile_n + n4];
            unsigned* dst = &Bs[kk * BS_STRIDE + n4];
            dst[0] = f2tf(v.x); dst[1] = f2tf(v.y);
            dst[2] = f2tf(v.z); dst[3] = f2tf(v.w);
        }
        __syncthreads();

#pragma unroll
        for (int ks = 0; ks < 4; ++ks) {
            if (ks * 8 >= width) break;
            const int k0 = ks * 8;
            unsigned a0 = As[(wm + grp)     * AS_STRIDE + k0 + tig];
            unsigned a1 = As[(wm + grp + 8) * AS_STRIDE + k0 + tig];
            unsigned a2 = As[(wm + grp)     * AS_STRIDE + k0 + tig + 4];
            unsigned a3 = As[(wm + grp + 8) * AS_STRIDE + k0 + tig + 4];
#pragma unroll
            for (int nt = 0; nt < 4; ++nt) {
                unsigned b0 = Bs[(k0 + tig)     * BS_STRIDE + wn + nt * 8 + grp];
                unsigned b1 = Bs[(k0 + tig + 4) * BS_STRIDE + wn + nt * 8 + grp];
                mma_tf32(acc[nt], a0, a1, a2, a3, b0, b1);
            }
        }
        __syncthreads();
    }

#pragma unroll
    for (int nt = 0; nt < 4; ++nt) {
        int gn0 = tile_n + wn + nt * 8 + tig * 2;
#pragma unroll
        for (int half = 0; half < 2; ++half) {
            int gm = tile_m + wm + grp + half * 8;
            if (gm >= M) continue;
#pragma unroll
            for (int cc = 0; cc < 2; ++cc) {
                int gn = gn0 + cc;
                if (gn >= Nout) continue;
                float v = acc[nt][half * 2 + cc] + (bias ? __ldg(&bias[gn]) : 0.f);
                if (mode == 0) {
                    out0[(size_t)gm * Dd + gn] = v;
                } else if (mode == 1) {
                    int ai = add_idx ? add_idx[gm] : gm;
                    v += add_src[(size_t)ai * Dd + gn];
                    out0[(size_t)gm * Dd + gn] = fmaxf(v, 0.f);
                } else if (mode == 2) {
                    atomicAdd(&out0[(size_t)scat_idx[gm] * Dd + gn], v);
                } else {  // dual
                    if (gn < Dd) {
                        out0[(size_t)gm * Dd + gn] = v;
                    } else {
                        int ai = add_idx[gm];
                        v += add_src[(size_t)ai * Dd + (gn - Dd)];
                        out1[(size_t)gm * Dd + (gn - Dd)] = fmaxf(v, 0.f);
                    }
                }
            }
        }
    }
}

// ---------------- per-node gather-sums from 4 pre-transformed tables -----------
__global__ void k_gsum4(const int* __restrict__ tok) {
    int i = blockIdx.x * blockDim.x + threadIdx.x;
    if (i >= Nn * Dd) return;
    int n = i / Dd, d = i - n * Dd;
    int4 t = ((const int4*)tok)[n];
    size_t o0 = (size_t)t.x * Dd + d, o1 = (size_t)t.y * Dd + d;
    size_t o2 = (size_t)t.z * Dd + d, o3 = (size_t)t.w * Dd + d;
    g_gsA[i] = g_embA[o0] + g_embA[o1] + g_embA[o2] + g_embA[o3];
    g_gsB[i] = g_embB[o0] + g_embB[o1] + g_embB[o2] + g_embB[o3];
    g_gsD[i] = g_embD[o0] + g_embD[o1] + g_embD[o2] + g_embD[o3];
    g_gsF[i] = g_embF[o0] + g_embF[o1] + g_embF[o2] + g_embF[o3];
}

// ---------------- edge layer-1, now pure elementwise ---------------------------
__global__ void k_edge_l1(const int* __restrict__ ea_tok,
                          const int* __restrict__ row, const int* __restrict__ col,
                          const float* __restrict__ eb1) {
    int i = blockIdx.x * blockDim.x + threadIdx.x;
    if (i >= Ee * Dd) return;
    int e = i / Dd, d = i - e * Dd;
    int4 t = ((const int4*)ea_tok)[e];
    float c = g_embC[(size_t)t.x * Dd + d] + g_embC[(size_t)t.y * Dd + d] +
              g_embC[(size_t)t.z * Dd + d] + g_embC[(size_t)t.w * Dd + d];
    int r = __ldg(&row[e]), q = __ldg(&col[e]);
    float v = g_gsA[(size_t)r * Dd + d] + g_gsB[(size_t)q * Dd + d] +
              c * g_sign[e] + __ldg(&eb1[d]);
    g_h[i] = fmaxf(v, 0.f);
}

// ---------------- tiny precompute helpers --------------------------------------
__global__ void k_b2(const float* __restrict__ eb2, const float* __restrict__ n1w1,
                     const float* __restrict__ n1b1) {
    int n = blockIdx.x * blockDim.x + threadIdx.x;
    if (n >= Dd) return;
    float s = n1b1[n];
    for (int k = 0; k < Dd; k++) s += eb2[k] * n1w1[(size_t)(Dd + k) * Dd + n];
    g_b2[n] = s;
}
__global__ void k_build_wcat(const float* __restrict__ ew2, const float* __restrict__ eb2) {
    int i = blockIdx.x * blockDim.x + threadIdx.x;
    if (i < Dd * 2 * Dd) {
        int k = i / (2 * Dd), n = i - k * 2 * Dd;
        g_wcat[i] = (n < Dd) ? ew2[(size_t)k * Dd + n] : g_w2p[(size_t)k * Dd + (n - Dd)];
    }
    if (i < 2 * Dd) g_bcat[i] = (i < Dd) ? eb2[i] : g_b2[i - Dd];
}

// ---------------- scatter-mean pieces ------------------------------------------
__global__ void k_cnt(const int* __restrict__ col) {
    int e = blockIdx.x * blockDim.x + threadIdx.x;
    if (e < Ee) atomicAdd(&g_cnt[col[e]], 1.f);
}
__global__ void k_aggnorm() {
    int i = blockIdx.x * blockDim.x + threadIdx.x;
    if (i >= Nn * Dd) return;
    g_agg[i] *= 1.f / fmaxf(g_cnt[i / Dd], 1.f);
}

// ---------------- graph layer norm ---------------------------------------------
__global__ void k_stats(const int* __restrict__ batch) {
    int n = blockIdx.x;
    float s = 0.f, q = 0.f;
    for (int d = threadIdx.x; d < Dd; d += 128) {
        float v = g_xenc[(size_t)n * Dd + d];
        s += v; q += v * v;
    }
#pragma unroll
    for (int o = 16; o; o >>= 1) {
        s += __shfl_down_sync(0xFFFFFFFFu, s, o);
        q += __shfl_down_sync(0xFFFFFFFFu, q, o);
    }
    __shared__ float ss[4], qq[4];
    int w = threadIdx.x >> 5, l = threadIdx.x & 31;
    if (l == 0) { ss[w] = s; qq[w] = q; }
    __syncthreads();
    if (threadIdx.x == 0) {
        s = ss[0] + ss[1] + ss[2] + ss[3];
        q = qq[0] + qq[1] + qq[2] + qq[3];
        int g = batch[n];
        atomicAdd(&g_gsum[g], s);
        atomicAdd(&g_gsq[g], q);
        atomicAdd(&g_gcnt[g], 1.f);
    }
}
__global__ void k_finalize() {
    int g = threadIdx.x;
    if (g < Gg) {
        float denom = fmaxf(g_gcnt[g] * (float)Dd, 1.f);
        float mean = g_gsum[g] / denom;
        float var = g_gsq[g] / denom - mean * mean;
        g_gmean[g] = mean;
        g_grstd[g] = rsqrtf(var + EPSv);
    }
}
__global__ void k_apply(const int* __restrict__ batch,
                        const float* __restrict__ lnw, const float* __restrict__ lnb,
                        float* __restrict__ out) {
    int i = blockIdx.x * blockDim.x + threadIdx.x;
    if (i >= Nn * Dd) return;
    int n = i / Dd, d = i - n * Dd;
    int g = batch[n];
    out[i] = (g_xenc[i] - g_gmean[g]) * g_grstd[g] * lnw[d] + lnb[d];
}

// ---------------- launch --------------------------------------------------------
static float* symf(const void* s) {
    void* p = nullptr;
    cudaGetSymbolAddress(&p, s);
    return (float*)p;
}

extern "C" void kernel_launch(void* const* d_in, const int* in_sizes, int n_in,
                              void* d_out, int out_size) {
    const int*   x_tok  = (const int*)d_in[0];
    const int*   ea_tok = (const int*)d_in[1];
    const int*   eidx   = (const int*)d_in[2];
    const int*   ase    = (const int*)d_in[3];
    const int*   batch  = (const int*)d_in[4];
    const float* emb    = (const float*)d_in[5];
    const float* ew1  = (const float*)d_in[6];
    const float* eb1  = (const float*)d_in[7];
    const float* ew2  = (const float*)d_in[8];
    const float* eb2  = (const float*)d_in[9];
    const float* n1w1 = (const float*)d_in[10];
    const float* n1b1 = (const float*)d_in[11];
    const float* n1w2 = (const float*)d_in[12];
    const float* n1b2 = (const float*)d_in[13];
    const float* n2w1 = (const float*)d_in[14];
    const float* n2b1 = (const float*)d_in[15];
    const float* n2w2 = (const float*)d_in[16];
    const float* n2b2 = (const float*)d_in[17];
    const float* lnw  = (const float*)d_in[18];
    const float* lnb  = (const float*)d_in[19];

    const int* row = eidx;
    const int* col = eidx + Ee;

    float* out = (float*)d_out;
    float* edge_out = out + (size_t)Nn * Dd;

    float* pembA = symf(g_embA); float* pembB = symf(g_embB);
    float* pembC = symf(g_embC); float* pembD = symf(g_embD);
    float* pembF = symf(g_embF);
    float* pgsD  = symf(g_gsD);  float* pgsF  = symf(g_gsF);
    float* ph    = symf(g_h);    float* pm    = symf(g_m);
    float* pagg  = symf(g_agg);  float* pxenc = symf(g_xenc);
    float* pw2p  = symf(g_w2p);  float* pwcat = symf(g_wcat);
    float* pbcat = symf(g_bcat);

    const int T256 = 256;
    k_zero<<<2048, T256>>>();
    k_sign_init<<<(Ee + T256 - 1) / T256, T256>>>();
    k_sign_set<<<(Ee / 2 + T256 - 1) / T256, T256>>>(ase);

    // precompute emb @ {Wa, Wb, Wc, Wd, Wf}  (each 3000x300x300)
    dim3 gV((Vv + 63) / 64, 5);
    k_gemm_tc<<<gV, T256>>>(Vv, Dd, emb, nullptr, ew1,            Dd, nullptr, pembA, nullptr, nullptr, nullptr, nullptr, 0);
    k_gemm_tc<<<gV, T256>>>(Vv, Dd, emb, nullptr, ew1 + 300*300,  Dd, nullptr, pembB, nullptr, nullptr, nullptr, nullptr, 0);
    k_gemm_tc<<<gV, T256>>>(Vv, Dd, emb, nullptr, ew1 + 600*300,  Dd, nullptr, pembC, nullptr, nullptr, nullptr, nullptr, 0);
    k_gemm_tc<<<gV, T256>>>(Vv, Dd, emb, nullptr, n1w1,           Dd, nullptr, pembD, nullptr, nullptr, nullptr, nullptr, 0);
    k_gemm_tc<<<gV, T256>>>(Vv, Dd, emb, nullptr, n2w1,           Dd, nullptr, pembF, nullptr, nullptr, nullptr, nullptr, 0);
    // w2p = ew2 @ We ; bcat/wcat assembly
    dim3 gW((Dd + 63) / 64, 5);
    k_gemm_tc<<<gW, T256>>>(Dd, Dd, ew2, nullptr, n1w1 + 300*300, Dd, nullptr, pw2p, nullptr, nullptr, nullptr, nullptr, 0);
    k_b2<<<2, 150>>>(eb2, n1w1, n1b1);
    k_build_wcat<<<(Dd * 2 * Dd + T256 - 1) / T256, T256>>>(ew2, eb2);

    // per-node gather sums + edge layer-1 elementwise
    k_gsum4<<<(Nn * Dd + T256 - 1) / T256, T256>>>(x_tok);
    k_edge_l1<<<(Ee * Dd + T256 - 1) / T256, T256>>>(ea_tok, row, col, eb1);

    // dual GEMM: edge_enc (plain) + node1 hidden (relu + gsD[row])
    dim3 gE2((Ee + 63) / 64, 10);
    k_gemm_tc<<<gE2, T256>>>(Ee, 2 * Dd, ph, nullptr, pwcat, 2 * Dd, pbcat,
                             edge_out, pm, pgsD, row, nullptr, 3);
    // node1 layer-2 with fused scatter-add into agg
    k_cnt<<<(Ee + T256 - 1) / T256, T256>>>(col);
    dim3 gE((Ee + 63) / 64, 5);
    k_gemm_tc<<<gE, T256>>>(Ee, Dd, pm, nullptr, n1w2, Dd, n1b2,
                            pagg, nullptr, nullptr, nullptr, col, 2);
    k_aggnorm<<<(Nn * Dd + T256 - 1) / T256, T256>>>();
    // node2 MLP
    dim3 gN((Nn + 63) / 64, 5);
    k_gemm_tc<<<gN, T256>>>(Nn, Dd, pagg, nullptr, n2w1 + 300*300, Dd, n2b1,
                            ph, nullptr, pgsF, nullptr, nullptr, 1);
    k_gemm_tc<<<gN, T256>>>(Nn, Dd, ph, nullptr, n2w2, Dd, n2b2,
                            pxenc, nullptr, nullptr, nullptr, nullptr, 0);
    // graph layer norm
    k_stats<<<Nn, 128>>>(batch);
    k_finalize<<<1, 128>>>();
    k_apply<<<(Nn * Dd + T256 - 1) / T256, T256>>>(batch, lnw, lnb, out);
}

// round 5
// speedup vs baseline: 8.6681x; 1.9081x over previous
#include <cuda_runtime.h>
#include <cstdint>

#define Nn 100000
#define Ee 400000
#define Dd 300
#define Vv 3000
#define Gg 128
#define EPSv 1e-5f

// ---------------- scratch (device globals) ------------------------------------
__device__ __align__(16) float g_embA[(size_t)Vv * Dd];
__device__ __align__(16) float g_embB[(size_t)Vv * Dd];
__device__ __align__(16) float g_embC[(size_t)Vv * Dd];
__device__ __align__(16) float g_embD[(size_t)Vv * Dd];
__device__ __align__(16) float g_embF[(size_t)Vv * Dd];
__device__ __align__(16) float g_gsA [(size_t)Nn * Dd];
__device__ __align__(16) float g_gsB [(size_t)Nn * Dd];
__device__ __align__(16) float g_gsD [(size_t)Nn * Dd];
__device__ __align__(16) float g_gsF [(size_t)Nn * Dd];
__device__ __align__(16) float g_h   [(size_t)Ee * Dd];   // h1, later node2 hidden (first Nn rows)
__device__ __align__(16) float g_agg [(size_t)Nn * Dd];   // aggsum of h2
__device__ __align__(16) float g_xenc[(size_t)Nn * Dd];
__device__ __align__(16) float g_w2p [Dd * Dd];           // ew2 @ n1w1_hi
__device__ __align__(16) float g_w12 [Dd * Dd];           // n1w2 @ n2w1_hi
__device__ __align__(16) float g_wcat[Dd * 2 * Dd];       // [300][600] = [ew2 | w2p]
__device__ float g_bcat[2 * Dd];
__device__ float g_b2[Dd];
__device__ float g_bb[Dd];                                // n1b2 @ n2w1_hi
__device__ float g_cnt[Nn];
__device__ float g_sign[Ee];
__device__ float g_gsum[Gg], g_gsq[Gg], g_gcnt[Gg], g_gmean[Gg], g_grstd[Gg];

// ---------------- init kernels -------------------------------------------------
__global__ void k_zero() {
    long long i = (long long)blockIdx.x * blockDim.x + threadIdx.x;
    long long stride = (long long)gridDim.x * blockDim.x;
    for (long long j = i; j < (long long)Nn * Dd; j += stride) g_agg[j] = 0.f;
    for (long long j = i; j < Nn; j += stride) g_cnt[j] = 0.f;
    if (i < Gg) { g_gsum[i] = 0.f; g_gsq[i] = 0.f; g_gcnt[i] = 0.f; }
}
__global__ void k_sign_init() {
    int i = blockIdx.x * blockDim.x + threadIdx.x;
    if (i < Ee) g_sign[i] = 1.f;
}
__global__ void k_sign_set(const int* __restrict__ ase) {
    int i = blockIdx.x * blockDim.x + threadIdx.x;
    if (i < Ee / 2) g_sign[ase[i]] = -1.f;
}

// ---------------- mma / cp.async helpers ---------------------------------------
__device__ __forceinline__ void mma_tf32(float* c, unsigned a0, unsigned a1,
                                         unsigned a2, unsigned a3,
                                         unsigned b0, unsigned b1) {
    asm volatile(
        "mma.sync.aligned.m16n8k8.row.col.f32.tf32.tf32.f32 "
        "{%0,%1,%2,%3}, {%4,%5,%6,%7}, {%8,%9}, {%0,%1,%2,%3};"
        : "+f"(c[0]), "+f"(c[1]), "+f"(c[2]), "+f"(c[3])
        : "r"(a0), "r"(a1), "r"(a2), "r"(a3), "r"(b0), "r"(b1));
}
__device__ __forceinline__ void cpa16(unsigned int dst, const void* src, bool p) {
    int sz = p ? 16 : 0;
    asm volatile("cp.async.cg.shared.global [%0], [%1], 16, %2;"
                 :: "r"(dst), "l"(src), "r"(sz));
}
__device__ __forceinline__ void cpa_commit() {
    asm volatile("cp.async.commit_group;");
}

// ---------------- tensor-core GEMM, K fixed = 300 ------------------------------
// BM=128, BN=64, BK=16, double-buffered cp.async, warp tile 32x32.
// modes: 0 plain (+bias if set) -> out0
//        3 dual Nout=600: gn<300 -> out0 = v+bias; gn>=300 ->
//          t = relu(v+bias+add_src[add_idx[m]*300+gn-300]); atomicAdd(out1[scat[m]*300+gn-300], t)
//        5 node2-l1: c=cnt[m]; out0 = relu(v/max(c,1) + bias + add_src[m*300+gn] + (c>0?bias2:0))
#define BMt 128
#define BNt 64
#define BKt 16
#define AS_STR 20
#define BS_STR 72
#define NCHUNK 19

__global__ __launch_bounds__(256) void k_gemm_tc(
    int M, int Nout,
    const float* __restrict__ A, const int* __restrict__ aidx,
    const float* __restrict__ W, int ldw,
    const float* __restrict__ bias, const float* __restrict__ bias2,
    float* __restrict__ out0, float* __restrict__ out1,
    const float* __restrict__ add_src, const int* __restrict__ add_idx,
    const int* __restrict__ scat_idx, const float* __restrict__ cntv,
    int mode)
{
    __shared__ float As[2][BMt * AS_STR];
    __shared__ float Bs[2][BKt * BS_STR];

    const int tid = threadIdx.x;
    const int lane = tid & 31, grp = lane >> 2, tig = lane & 3;
    const int w = tid >> 5;
    const int wm = (w & 3) * 32, wn = (w >> 2) * 32;
    const int tile_n = blockIdx.x * BNt;
    const int tile_m = blockIdx.y * BMt;

    // per-thread A row pointers (2 rows) and slot offsets
    const float* rp[2];
#pragma unroll
    for (int it = 0; it < 2; ++it) {
        int m = (tid >> 2) + it * 64;
        int gm = tile_m + m; if (gm >= M) gm = M - 1;
        int r = aidx ? __ldg(&aidx[gm]) : gm;
        rp[it] = A + (size_t)r * Dd;
    }
    const int ag  = (tid & 3) * 4;       // A k-offset within chunk
    const int bk  = tid >> 4;            // B row within chunk
    const int bn4 = (tid & 15) * 4;      // B col group

    unsigned int sA[2][2], sB[2];
#pragma unroll
    for (int b = 0; b < 2; ++b) {
#pragma unroll
        for (int it = 0; it < 2; ++it) {
            int m = (tid >> 2) + it * 64;
            sA[b][it] = (unsigned int)__cvta_generic_to_shared(&As[b][m * AS_STR + ag]);
        }
        sB[b] = (unsigned int)__cvta_generic_to_shared(&Bs[b][bk * BS_STR + bn4]);
    }

    float acc[2][4][4];
#pragma unroll
    for (int mt = 0; mt < 2; mt++)
#pragma unroll
        for (int nt = 0; nt < 4; nt++)
#pragma unroll
            for (int q = 0; q < 4; q++) acc[mt][nt][q] = 0.f;

    // chunk loader
    auto load_chunk = [&](int c, int b) {
        int koff = c * BKt;
        int width = 300 - koff; if (width > BKt) width = BKt;
        cpa16(sA[b][0], rp[0] + koff + ag, ag < width);
        cpa16(sA[b][1], rp[1] + koff + ag, ag < width);
        bool pb = (bk < width) && (tile_n + bn4 < Nout);
        cpa16(sB[b], W + (size_t)(koff + bk) * ldw + tile_n + bn4, pb);
    };

    load_chunk(0, 0);
    cpa_commit();

    for (int c = 0; c < NCHUNK; ++c) {
        if (c + 1 < NCHUNK) { load_chunk(c + 1, (c + 1) & 1); cpa_commit(); }
        if (c + 1 < NCHUNK) asm volatile("cp.async.wait_group 1;");
        else                asm volatile("cp.async.wait_group 0;");
        __syncthreads();

        const float* as = As[c & 1];
        const float* bs = Bs[c & 1];
#pragma unroll
        for (int ks = 0; ks < 2; ++ks) {
            const int k0 = ks * 8;
            unsigned af[2][4], bf[4][2];
#pragma unroll
            for (int mt = 0; mt < 2; ++mt) {
                int r0 = (wm + mt * 16 + grp) * AS_STR;
                af[mt][0] = __float_as_uint(as[r0 + k0 + tig]);
                af[mt][1] = __float_as_uint(as[r0 + 8 * AS_STR + k0 + tig]);
                af[mt][2] = __float_as_uint(as[r0 + k0 + tig + 4]);
                af[mt][3] = __float_as_uint(as[r0 + 8 * AS_STR + k0 + tig + 4]);
            }
#pragma unroll
            for (int nt = 0; nt < 4; ++nt) {
                bf[nt][0] = __float_as_uint(bs[(k0 + tig) * BS_STR + wn + nt * 8 + grp]);
                bf[nt][1] = __float_as_uint(bs[(k0 + tig + 4) * BS_STR + wn + nt * 8 + grp]);
            }
#pragma unroll
            for (int mt = 0; mt < 2; ++mt)
#pragma unroll
                for (int nt = 0; nt < 4; ++nt)
                    mma_tf32(acc[mt][nt], af[mt][0], af[mt][1], af[mt][2], af[mt][3],
                             bf[nt][0], bf[nt][1]);
        }
        __syncthreads();
    }

    // ---- epilogue ----
#pragma unroll
    for (int mt = 0; mt < 2; ++mt) {
#pragma unroll
        for (int half = 0; half < 2; ++half) {
            int gm = tile_m + wm + mt * 16 + grp + half * 8;
            if (gm >= M) continue;
#pragma unroll
            for (int nt = 0; nt < 4; ++nt) {
#pragma unroll
                for (int cc = 0; cc < 2; ++cc) {
                    int gn = tile_n + wn + nt * 8 + tig * 2 + cc;
                    if (gn >= Nout) continue;
                    float v = acc[mt][nt][half * 2 + cc];
                    if (mode == 0) {
                        if (bias) v += __ldg(&bias[gn]);
                        out0[(size_t)gm * Dd + gn] = v;
                    } else if (mode == 3) {
                        v += __ldg(&bias[gn]);
                        if (gn < Dd) {
                            out0[(size_t)gm * Dd + gn] = v;
                        } else {
                            int gn2 = gn - Dd;
                            v += add_src[(size_t)__ldg(&add_idx[gm]) * Dd + gn2];
                            v = fmaxf(v, 0.f);
                            atomicAdd(&out1[(size_t)__ldg(&scat_idx[gm]) * Dd + gn2], v);
                        }
                    } else {  // mode 5
                        float ct = __ldg(&cntv[gm]);
                        v = v / fmaxf(ct, 1.f) + __ldg(&bias[gn]) +
                            add_src[(size_t)gm * Dd + gn] +
                            (ct > 0.f ? __ldg(&bias2[gn]) : 0.f);
                        out0[(size_t)gm * Dd + gn] = fmaxf(v, 0.f);
                    }
                }
            }
        }
    }
}

// ---------------- per-node gather-sums from 4 pre-transformed tables -----------
__global__ void k_gsum4(const int* __restrict__ tok) {
    int i = blockIdx.x * blockDim.x + threadIdx.x;
    if (i >= Nn * Dd) return;
    int n = i / Dd, d = i - n * Dd;
    int4 t = ((const int4*)tok)[n];
    size_t o0 = (size_t)t.x * Dd + d, o1 = (size_t)t.y * Dd + d;
    size_t o2 = (size_t)t.z * Dd + d, o3 = (size_t)t.w * Dd + d;
    g_gsA[i] = g_embA[o0] + g_embA[o1] + g_embA[o2] + g_embA[o3];
    g_gsB[i] = g_embB[o0] + g_embB[o1] + g_embB[o2] + g_embB[o3];
    g_gsD[i] = g_embD[o0] + g_embD[o1] + g_embD[o2] + g_embD[o3];
    g_gsF[i] = g_embF[o0] + g_embF[o1] + g_embF[o2] + g_embF[o3];
}

// ---------------- edge layer-1, pure elementwise --------------------------------
__global__ void k_edge_l1(const int* __restrict__ ea_tok,
                          const int* __restrict__ row, const int* __restrict__ col,
                          const float* __restrict__ eb1) {
    int i = blockIdx.x * blockDim.x + threadIdx.x;
    if (i >= Ee * Dd) return;
    int e = i / Dd, d = i - e * Dd;
    int4 t = ((const int4*)ea_tok)[e];
    float c = g_embC[(size_t)t.x * Dd + d] + g_embC[(size_t)t.y * Dd + d] +
              g_embC[(size_t)t.z * Dd + d] + g_embC[(size_t)t.w * Dd + d];
    int r = __ldg(&row[e]), q = __ldg(&col[e]);
    float v = g_gsA[(size_t)r * Dd + d] + g_gsB[(size_t)q * Dd + d] +
              c * g_sign[e] + __ldg(&eb1[d]);
    g_h[i] = fmaxf(v, 0.f);
}

// ---------------- tiny precompute helpers ---------------------------------------
__global__ void k_vecmat(float* __restrict__ out, const float* __restrict__ vec,
                         const float* __restrict__ mat, const float* __restrict__ addv) {
    int n = blockIdx.x * blockDim.x + threadIdx.x;
    if (n >= Dd) return;
    float s = addv ? addv[n] : 0.f;
    for (int k = 0; k < Dd; k++) s += vec[k] * mat[(size_t)k * Dd + n];
    out[n] = s;
}
__global__ void k_build_wcat(const float* __restrict__ ew2, const float* __restrict__ eb2) {
    int i = blockIdx.x * blockDim.x + threadIdx.x;
    if (i < Dd * 2 * Dd) {
        int k = i / (2 * Dd), n = i - k * 2 * Dd;
        g_wcat[i] = (n < Dd) ? ew2[(size_t)k * Dd + n] : g_w2p[(size_t)k * Dd + (n - Dd)];
    }
    if (i < 2 * Dd) g_bcat[i] = (i < Dd) ? eb2[i] : g_b2[i - Dd];
}

// ---------------- edge counts ---------------------------------------------------
__global__ void k_cnt(const int* __restrict__ col) {
    int e = blockIdx.x * blockDim.x + threadIdx.x;
    if (e < Ee) atomicAdd(&g_cnt[col[e]], 1.f);
}

// ---------------- graph layer norm ----------------------------------------------
__global__ void k_stats(const int* __restrict__ batch) {
    int n = blockIdx.x;
    float s = 0.f, q = 0.f;
    for (int d = threadIdx.x; d < Dd; d += 128) {
        float v = g_xenc[(size_t)n * Dd + d];
        s += v; q += v * v;
    }
#pragma unroll
    for (int o = 16; o; o >>= 1) {
        s += __shfl_down_sync(0xFFFFFFFFu, s, o);
        q += __shfl_down_sync(0xFFFFFFFFu, q, o);
    }
    __shared__ float ss[4], qq[4];
    int w = threadIdx.x >> 5, l = threadIdx.x & 31;
    if (l == 0) { ss[w] = s; qq[w] = q; }
    __syncthreads();
    if (threadIdx.x == 0) {
        s = ss[0] + ss[1] + ss[2] + ss[3];
        q = qq[0] + qq[1] + qq[2] + qq[3];
        int g = batch[n];
        atomicAdd(&g_gsum[g], s);
        atomicAdd(&g_gsq[g], q);
        atomicAdd(&g_gcnt[g], 1.f);
    }
}
__global__ void k_finalize() {
    int g = threadIdx.x;
    if (g < Gg) {
        float denom = fmaxf(g_gcnt[g] * (float)Dd, 1.f);
        float mean = g_gsum[g] / denom;
        float var = g_gsq[g] / denom - mean * mean;
        g_gmean[g] = mean;
        g_grstd[g] = rsqrtf(var + EPSv);
    }
}
__global__ void k_apply(const int* __restrict__ batch,
                        const float* __restrict__ lnw, const float* __restrict__ lnb,
                        float* __restrict__ out) {
    int i = blockIdx.x * blockDim.x + threadIdx.x;
    if (i >= Nn * Dd) return;
    int n = i / Dd, d = i - n * Dd;
    int g = batch[n];
    out[i] = (g_xenc[i] - g_gmean[g]) * g_grstd[g] * lnw[d] + lnb[d];
}

// ---------------- launch ---------------------------------------------------------
static float* symf(const void* s) {
    void* p = nullptr;
    cudaGetSymbolAddress(&p, s);
    return (float*)p;
}

extern "C" void kernel_launch(void* const* d_in, const int* in_sizes, int n_in,
                              void* d_out, int out_size) {
    const int*   x_tok  = (const int*)d_in[0];
    const int*   ea_tok = (const int*)d_in[1];
    const int*   eidx   = (const int*)d_in[2];
    const int*   ase    = (const int*)d_in[3];
    const int*   batch  = (const int*)d_in[4];
    const float* emb    = (const float*)d_in[5];
    const float* ew1  = (const float*)d_in[6];
    const float* eb1  = (const float*)d_in[7];
    const float* ew2  = (const float*)d_in[8];
    const float* eb2  = (const float*)d_in[9];
    const float* n1w1 = (const float*)d_in[10];
    const float* n1b1 = (const float*)d_in[11];
    const float* n1w2 = (const float*)d_in[12];
    const float* n1b2 = (const float*)d_in[13];
    const float* n2w1 = (const float*)d_in[14];
    const float* n2b1 = (const float*)d_in[15];
    const float* n2w2 = (const float*)d_in[16];
    const float* n2b2 = (const float*)d_in[17];
    const float* lnw  = (const float*)d_in[18];
    const float* lnb  = (const float*)d_in[19];

    const int* row = eidx;
    const int* col = eidx + Ee;

    float* out = (float*)d_out;
    float* edge_out = out + (size_t)Nn * Dd;

    float* pembA = symf(g_embA); float* pembB = symf(g_embB);
    float* pembC = symf(g_embC); float* pembD = symf(g_embD);
    float* pembF = symf(g_embF);
    float* pgsD  = symf(g_gsD);  float* pgsF  = symf(g_gsF);
    float* ph    = symf(g_h);
    float* pagg  = symf(g_agg);  float* pxenc = symf(g_xenc);
    float* pw2p  = symf(g_w2p);  float* pw12  = symf(g_w12);
    float* pwcat = symf(g_wcat); float* pbcat = symf(g_bcat);
    float* pb2   = symf(g_b2);   float* pbb   = symf(g_bb);
    float* pcnt  = symf(g_cnt);

    const int T256 = 256;
    k_zero<<<2048, T256>>>();
    k_sign_init<<<(Ee + T256 - 1) / T256, T256>>>();
    k_sign_set<<<(Ee / 2 + T256 - 1) / T256, T256>>>(ase);

    // precompute emb @ {Wa, Wb, Wc, Wd, Wf}
    dim3 gV(5, (Vv + BMt - 1) / BMt);
    k_gemm_tc<<<gV, T256>>>(Vv, Dd, emb, nullptr, ew1,           Dd, nullptr, nullptr, pembA, nullptr, nullptr, nullptr, nullptr, nullptr, 0);
    k_gemm_tc<<<gV, T256>>>(Vv, Dd, emb, nullptr, ew1 + 300*300, Dd, nullptr, nullptr, pembB, nullptr, nullptr, nullptr, nullptr, nullptr, 0);
    k_gemm_tc<<<gV, T256>>>(Vv, Dd, emb, nullptr, ew1 + 600*300, Dd, nullptr, nullptr, pembC, nullptr, nullptr, nullptr, nullptr, nullptr, 0);
    k_gemm_tc<<<gV, T256>>>(Vv, Dd, emb, nullptr, n1w1,          Dd, nullptr, nullptr, pembD, nullptr, nullptr, nullptr, nullptr, nullptr, 0);
    k_gemm_tc<<<gV, T256>>>(Vv, Dd, emb, nullptr, n2w1,          Dd, nullptr, nullptr, pembF, nullptr, nullptr, nullptr, nullptr, nullptr, 0);
    // w2p = ew2 @ n1w1_hi ; W12 = n1w2 @ n2w1_hi ; b2 ; bb ; wcat
    dim3 gW(5, (Dd + BMt - 1) / BMt);
    k_gemm_tc<<<gW, T256>>>(Dd, Dd, ew2,  nullptr, n1w1 + 300*300, Dd, nullptr, nullptr, pw2p, nullptr, nullptr, nullptr, nullptr, nullptr, 0);
    k_gemm_tc<<<gW, T256>>>(Dd, Dd, n1w2, nullptr, n2w1 + 300*300, Dd, nullptr, nullptr, pw12, nullptr, nullptr, nullptr, nullptr, nullptr, 0);
    k_vecmat<<<3, 128>>>(pb2, eb2,  n1w1 + 300*300, n1b1);
    k_vecmat<<<3, 128>>>(pbb, n1b2, n2w1 + 300*300, nullptr);
    k_build_wcat<<<(Dd * 2 * Dd + T256 - 1) / T256, T256>>>(ew2, eb2);

    // per-node gather sums + edge layer-1 elementwise + counts
    k_gsum4<<<(Nn * Dd + T256 - 1) / T256, T256>>>(x_tok);
    k_edge_l1<<<(Ee * Dd + T256 - 1) / T256, T256>>>(ea_tok, row, col, eb1);
    k_cnt<<<(Ee + T256 - 1) / T256, T256>>>(col);

    // dual GEMM: edge_enc (store) + h2 (relu + gsD[row]) scattered into aggsum
    dim3 gE(10, (Ee + BMt - 1) / BMt);
    k_gemm_tc<<<gE, T256>>>(Ee, 2 * Dd, ph, nullptr, pwcat, 2 * Dd, pbcat, nullptr,
                            edge_out, pagg, pgsD, row, col, nullptr, 3);

    // node2 layer-1: hidden = relu(aggsum@W12/cnt + gsF + (cnt>0)bb + n2b1)
    dim3 gN(5, (Nn + BMt - 1) / BMt);
    k_gemm_tc<<<gN, T256>>>(Nn, Dd, pagg, nullptr, pw12, Dd, n2b1, pbb,
                            ph, nullptr, pgsF, nullptr, nullptr, pcnt, 5);
    // node2 layer-2
    k_gemm_tc<<<gN, T256>>>(Nn, Dd, ph, nullptr, n2w2, Dd, n2b2, nullptr,
                            pxenc, nullptr, nullptr, nullptr, nullptr, nullptr, 0);

    // graph layer norm
    k_stats<<<Nn, 128>>>(batch);
    k_finalize<<<1, 128>>>();
    k_apply<<<(Nn * Dd + T256 - 1) / T256, T256>>>(batch, lnw, lnb, out);
}

// round 6
// speedup vs baseline: 10.3472x; 1.1937x over previous
#include <cuda_runtime.h>
#include <cstdint>

#define Nn 100000
#define Ee 400000
#define Dd 300
#define Vv 3000
#define Gg 128
#define EPSv 1e-5f

// ---------------- scratch (device globals) ------------------------------------
__device__ __align__(16) float g_embA[(size_t)Vv * Dd];
__device__ __align__(16) float g_embB[(size_t)Vv * Dd];
__device__ __align__(16) float g_embC[(size_t)Vv * Dd];
__device__ __align__(16) float g_embD[(size_t)Vv * Dd];
__device__ __align__(16) float g_embF[(size_t)Vv * Dd];
__device__ __align__(16) float g_gsA [(size_t)Nn * Dd];
__device__ __align__(16) float g_gsB [(size_t)Nn * Dd];
__device__ __align__(16) float g_gsD [(size_t)Nn * Dd];
__device__ __align__(16) float g_gsF [(size_t)Nn * Dd];
__device__ __align__(16) float g_h   [(size_t)Ee * Dd];   // h1; later node2 hidden (first Nn rows)
__device__ __align__(16) float g_agg [(size_t)Nn * Dd];   // aggsum of h2
__device__ __align__(16) float g_xenc[(size_t)Nn * Dd];
__device__ __align__(16) float g_w2p [Dd * Dd];           // ew2 @ n1w1_hi
__device__ __align__(16) float g_w12 [Dd * Dd];           // n1w2 @ n2w1_hi
__device__ __align__(16) float g_wcat[Dd * 2 * Dd];       // [300][600] = [ew2 | w2p]
__device__ __align__(16) float g_bcat[2 * Dd];
__device__ __align__(16) float g_b2[Dd];
__device__ __align__(16) float g_bb[Dd];                  // n1b2 @ n2w1_hi
__device__ float g_cnt[Nn];
__device__ float g_sign[Ee];
__device__ float g_gsum[Gg], g_gsq[Gg], g_gcnt[Gg], g_gmean[Gg], g_grstd[Gg];

// ---------------- merged init: zero agg/cnt/stats, sign=1 ----------------------
__global__ void k_init() {
    long long i = (long long)blockIdx.x * blockDim.x + threadIdx.x;
    long long stride = (long long)gridDim.x * blockDim.x;
    for (long long j = i; j < (long long)Nn * Dd; j += stride) g_agg[j] = 0.f;
    for (long long j = i; j < Nn; j += stride) g_cnt[j] = 0.f;
    for (long long j = i; j < Ee; j += stride) g_sign[j] = 1.f;
    if (i < Gg) { g_gsum[i] = 0.f; g_gsq[i] = 0.f; g_gcnt[i] = 0.f; }
}
// sign[ase]=-1 and degree histogram in one pass
__global__ void k_signset_cnt(const int* __restrict__ ase, const int* __restrict__ col) {
    int i = blockIdx.x * blockDim.x + threadIdx.x;
    if (i < Ee) atomicAdd(&g_cnt[col[i]], 1.f);
    if (i < Ee / 2) g_sign[ase[i]] = -1.f;
}

// ---------------- mma / cp.async / red helpers ---------------------------------
__device__ __forceinline__ void mma_tf32(float* c, unsigned a0, unsigned a1,
                                         unsigned a2, unsigned a3,
                                         unsigned b0, unsigned b1) {
    asm volatile(
        "mma.sync.aligned.m16n8k8.row.col.f32.tf32.tf32.f32 "
        "{%0,%1,%2,%3}, {%4,%5,%6,%7}, {%8,%9}, {%0,%1,%2,%3};"
        : "+f"(c[0]), "+f"(c[1]), "+f"(c[2]), "+f"(c[3])
        : "r"(a0), "r"(a1), "r"(a2), "r"(a3), "r"(b0), "r"(b1));
}
__device__ __forceinline__ void cpa16(unsigned int dst, const void* src, bool p) {
    int sz = p ? 16 : 0;
    asm volatile("cp.async.cg.shared.global [%0], [%1], 16, %2;"
                 :: "r"(dst), "l"(src), "r"(sz));
}
__device__ __forceinline__ void cpa_commit() {
    asm volatile("cp.async.commit_group;");
}
__device__ __forceinline__ void red_v2(float* p, float2 v) {
    asm volatile("red.global.add.v2.f32 [%0], {%1, %2};"
                 :: "l"(p), "f"(v.x), "f"(v.y) : "memory");
}

// ---------------- tensor-core GEMM, K fixed = 300 ------------------------------
// BM=128, BN=64, BK=16, double-buffered cp.async, warp tile 32x32.
// MODE 0: out0 = v (+bias)
// MODE 3: dual Nout=600: gn<300 -> out0 = v+bias; gn>=300 ->
//         t = relu(v+bias+add_src[add_idx[m]*300+gn-300]); red.v2(out1[scat[m]*300+gn-300], t)
// MODE 5: c=cnt[m]; out0 = relu(v/max(c,1) + bias + add_src[m*300+gn] + (c>0?bias2:0))
#define BMt 128
#define BNt 64
#define BKt 16
#define AS_STR 20
#define BS_STR 72
#define NCHUNK 19

template <int MODE>
__global__ __launch_bounds__(256) void k_gemm_tc(
    int M, int Nout,
    const float* __restrict__ A, const int* __restrict__ aidx,
    const float* __restrict__ W, int ldw,
    const float* __restrict__ bias, const float* __restrict__ bias2,
    float* __restrict__ out0, float* __restrict__ out1,
    const float* __restrict__ add_src, const int* __restrict__ add_idx,
    const int* __restrict__ scat_idx, const float* __restrict__ cntv)
{
    __shared__ float As[2][BMt * AS_STR];
    __shared__ float Bs[2][BKt * BS_STR];

    const int tid = threadIdx.x;
    const int lane = tid & 31, grp = lane >> 2, tig = lane & 3;
    const int w = tid >> 5;
    const int wm = (w & 3) * 32, wn = (w >> 2) * 32;
    const int tile_n = blockIdx.x * BNt;
    const int tile_m = blockIdx.y * BMt;

    const float* rp[2];
#pragma unroll
    for (int it = 0; it < 2; ++it) {
        int m = (tid >> 2) + it * 64;
        int gm = tile_m + m; if (gm >= M) gm = M - 1;
        int r = aidx ? __ldg(&aidx[gm]) : gm;
        rp[it] = A + (size_t)r * Dd;
    }
    const int ag  = (tid & 3) * 4;
    const int bk  = tid >> 4;
    const int bn4 = (tid & 15) * 4;

    unsigned int sA[2][2], sB[2];
#pragma unroll
    for (int b = 0; b < 2; ++b) {
#pragma unroll
        for (int it = 0; it < 2; ++it) {
            int m = (tid >> 2) + it * 64;
            sA[b][it] = (unsigned int)__cvta_generic_to_shared(&As[b][m * AS_STR + ag]);
        }
        sB[b] = (unsigned int)__cvta_generic_to_shared(&Bs[b][bk * BS_STR + bn4]);
    }

    float acc[2][4][4];
#pragma unroll
    for (int mt = 0; mt < 2; mt++)
#pragma unroll
        for (int nt = 0; nt < 4; nt++)
#pragma unroll
            for (int q = 0; q < 4; q++) acc[mt][nt][q] = 0.f;

    auto load_chunk = [&](int c, int b) {
        int koff = c * BKt;
        int width = 300 - koff; if (width > BKt) width = BKt;
        cpa16(sA[b][0], rp[0] + koff + ag, ag < width);
        cpa16(sA[b][1], rp[1] + koff + ag, ag < width);
        bool pb = (bk < width) && (tile_n + bn4 < Nout);
        cpa16(sB[b], W + (size_t)(koff + bk) * ldw + tile_n + bn4, pb);
    };

    load_chunk(0, 0);
    cpa_commit();

    for (int c = 0; c < NCHUNK; ++c) {
        if (c + 1 < NCHUNK) { load_chunk(c + 1, (c + 1) & 1); cpa_commit(); }
        if (c + 1 < NCHUNK) asm volatile("cp.async.wait_group 1;");
        else                asm volatile("cp.async.wait_group 0;");
        __syncthreads();

        const float* as = As[c & 1];
        const float* bs = Bs[c & 1];
#pragma unroll
        for (int ks = 0; ks < 2; ++ks) {
            const int k0 = ks * 8;
            unsigned af[2][4], bf[4][2];
#pragma unroll
            for (int mt = 0; mt < 2; ++mt) {
                int r0 = (wm + mt * 16 + grp) * AS_STR;
                af[mt][0] = __float_as_uint(as[r0 + k0 + tig]);
                af[mt][1] = __float_as_uint(as[r0 + 8 * AS_STR + k0 + tig]);
                af[mt][2] = __float_as_uint(as[r0 + k0 + tig + 4]);
                af[mt][3] = __float_as_uint(as[r0 + 8 * AS_STR + k0 + tig + 4]);
            }
#pragma unroll
            for (int nt = 0; nt < 4; ++nt) {
                bf[nt][0] = __float_as_uint(bs[(k0 + tig) * BS_STR + wn + nt * 8 + grp]);
                bf[nt][1] = __float_as_uint(bs[(k0 + tig + 4) * BS_STR + wn + nt * 8 + grp]);
            }
#pragma unroll
            for (int mt = 0; mt < 2; ++mt)
#pragma unroll
                for (int nt = 0; nt < 4; ++nt)
                    mma_tf32(acc[mt][nt], af[mt][0], af[mt][1], af[mt][2], af[mt][3],
                             bf[nt][0], bf[nt][1]);
        }
        __syncthreads();
    }

    // ---- epilogue (pairs: gn even, never straddles 300) ----
    const bool hi_half = (tile_n + wn + BNt / 2 - 1 + 31) >= Dd;  // any gn>=300 possible
#pragma unroll
    for (int mt = 0; mt < 2; ++mt) {
#pragma unroll
        for (int half = 0; half < 2; ++half) {
            int gm = tile_m + wm + mt * 16 + grp + half * 8;
            if (gm >= M) continue;
            int ai = 0, si = 0;
            float ct = 0.f, inv = 0.f;
            if (MODE == 3) {
                if (hi_half) { ai = __ldg(&add_idx[gm]); si = __ldg(&scat_idx[gm]); }
            }
            if (MODE == 5) { ct = __ldg(&cntv[gm]); inv = 1.f / fmaxf(ct, 1.f); }
#pragma unroll
            for (int nt = 0; nt < 4; ++nt) {
                int gn = tile_n + wn + nt * 8 + tig * 2;
                if (gn >= Nout) continue;
                float2 v = make_float2(acc[mt][nt][half * 2], acc[mt][nt][half * 2 + 1]);
                if (MODE == 0) {
                    if (bias) {
                        float2 b = __ldg((const float2*)&bias[gn]);
                        v.x += b.x; v.y += b.y;
                    }
                    *(float2*)&out0[(size_t)gm * Dd + gn] = v;
                } else if (MODE == 3) {
                    float2 b = __ldg((const float2*)&bias[gn]);
                    v.x += b.x; v.y += b.y;
                    if (gn < Dd) {
                        *(float2*)&out0[(size_t)gm * Dd + gn] = v;
                    } else {
                        int gn2 = gn - Dd;
                        float2 a = *(const float2*)&add_src[(size_t)ai * Dd + gn2];
                        v.x = fmaxf(v.x + a.x, 0.f);
                        v.y = fmaxf(v.y + a.y, 0.f);
                        red_v2(&out1[(size_t)si * Dd + gn2], v);
                    }
                } else {  // MODE 5
                    float2 b = __ldg((const float2*)&bias[gn]);
                    float2 a = *(const float2*)&add_src[(size_t)gm * Dd + gn];
                    float2 b2 = make_float2(0.f, 0.f);
                    if (ct > 0.f) b2 = __ldg((const float2*)&bias2[gn]);
                    v.x = fmaxf(v.x * inv + b.x + b2.x + a.x, 0.f);
                    v.y = fmaxf(v.y * inv + b.y + b2.y + a.y, 0.f);
                    *(float2*)&out0[(size_t)gm * Dd + gn] = v;
                }
            }
        }
    }
}

// ---------------- gather-sum of 2 pre-transformed tables (float4/thread) -------
__global__ void k_gsum2(const int* __restrict__ tok,
                        const float* __restrict__ tA, const float* __restrict__ tB,
                        float* __restrict__ dA, float* __restrict__ dB) {
    int i = blockIdx.x * blockDim.x + threadIdx.x;
    if (i >= Nn * 75) return;
    int n = i / 75, d0 = (i - n * 75) * 4;
    int4 t = ((const int4*)tok)[n];
    size_t o0 = (size_t)t.x * Dd + d0, o1 = (size_t)t.y * Dd + d0;
    size_t o2 = (size_t)t.z * Dd + d0, o3 = (size_t)t.w * Dd + d0;
    float4 a0 = *(const float4*)&tA[o0], a1 = *(const float4*)&tA[o1];
    float4 a2 = *(const float4*)&tA[o2], a3 = *(const float4*)&tA[o3];
    float4 r;
    r.x = a0.x + a1.x + a2.x + a3.x; r.y = a0.y + a1.y + a2.y + a3.y;
    r.z = a0.z + a1.z + a2.z + a3.z; r.w = a0.w + a1.w + a2.w + a3.w;
    *(float4*)&dA[(size_t)n * Dd + d0] = r;
    float4 b0 = *(const float4*)&tB[o0], b1 = *(const float4*)&tB[o1];
    float4 b2 = *(const float4*)&tB[o2], b3 = *(const float4*)&tB[o3];
    r.x = b0.x + b1.x + b2.x + b3.x; r.y = b0.y + b1.y + b2.y + b3.y;
    r.z = b0.z + b1.z + b2.z + b3.z; r.w = b0.w + b1.w + b2.w + b3.w;
    *(float4*)&dB[(size_t)n * Dd + d0] = r;
}

// ---------------- edge layer-1 elementwise (float4/thread) ----------------------
__global__ void k_edge_l1(const int* __restrict__ ea_tok,
                          const int* __restrict__ row, const int* __restrict__ col,
                          const float* __restrict__ eb1) {
    int i = blockIdx.x * blockDim.x + threadIdx.x;
    if (i >= Ee * 75) return;
    int e = i / 75, d0 = (i - e * 75) * 4;
    int4 t = ((const int4*)ea_tok)[e];
    float4 c0 = *(const float4*)&g_embC[(size_t)t.x * Dd + d0];
    float4 c1 = *(const float4*)&g_embC[(size_t)t.y * Dd + d0];
    float4 c2 = *(const float4*)&g_embC[(size_t)t.z * Dd + d0];
    float4 c3 = *(const float4*)&g_embC[(size_t)t.w * Dd + d0];
    int r = __ldg(&row[e]), q = __ldg(&col[e]);
    float sg = g_sign[e];
    float4 ga = *(const float4*)&g_gsA[(size_t)r * Dd + d0];
    float4 gb = *(const float4*)&g_gsB[(size_t)q * Dd + d0];
    float4 bb = __ldg((const float4*)&eb1[d0]);
    float4 o;
    o.x = fmaxf(ga.x + gb.x + (c0.x + c1.x + c2.x + c3.x) * sg + bb.x, 0.f);
    o.y = fmaxf(ga.y + gb.y + (c0.y + c1.y + c2.y + c3.y) * sg + bb.y, 0.f);
    o.z = fmaxf(ga.z + gb.z + (c0.z + c1.z + c2.z + c3.z) * sg + bb.z, 0.f);
    o.w = fmaxf(ga.w + gb.w + (c0.w + c1.w + c2.w + c3.w) * sg + bb.w, 0.f);
    *(float4*)&g_h[(size_t)e * Dd + d0] = o;
}

// ---------------- tiny precompute helpers ---------------------------------------
__global__ void k_vecmat(float* __restrict__ out, const float* __restrict__ vec,
                         const float* __restrict__ mat, const float* __restrict__ addv) {
    int n = blockIdx.x * blockDim.x + threadIdx.x;
    if (n >= Dd) return;
    float s = addv ? addv[n] : 0.f;
    for (int k = 0; k < Dd; k++) s += vec[k] * mat[(size_t)k * Dd + n];
    out[n] = s;
}
__global__ void k_build_wcat(const float* __restrict__ ew2, const float* __restrict__ eb2) {
    int i = blockIdx.x * blockDim.x + threadIdx.x;
    if (i < Dd * 2 * Dd) {
        int k = i / (2 * Dd), n = i - k * 2 * Dd;
        g_wcat[i] = (n < Dd) ? ew2[(size_t)k * Dd + n] : g_w2p[(size_t)k * Dd + (n - Dd)];
    }
    if (i < 2 * Dd) g_bcat[i] = (i < Dd) ? eb2[i] : g_b2[i - Dd];
}

// ---------------- graph layer norm ----------------------------------------------
__global__ void k_stats(const int* __restrict__ batch) {
    int n = blockIdx.x;
    float s = 0.f, q = 0.f;
    for (int d = threadIdx.x; d < Dd; d += 128) {
        float v = g_xenc[(size_t)n * Dd + d];
        s += v; q += v * v;
    }
#pragma unroll
    for (int o = 16; o; o >>= 1) {
        s += __shfl_down_sync(0xFFFFFFFFu, s, o);
        q += __shfl_down_sync(0xFFFFFFFFu, q, o);
    }
    __shared__ float ss[4], qq[4];
    int w = threadIdx.x >> 5, l = threadIdx.x & 31;
    if (l == 0) { ss[w] = s; qq[w] = q; }
    __syncthreads();
    if (threadIdx.x == 0) {
        s = ss[0] + ss[1] + ss[2] + ss[3];
        q = qq[0] + qq[1] + qq[2] + qq[3];
        int g = batch[n];
        atomicAdd(&g_gsum[g], s);
        atomicAdd(&g_gsq[g], q);
        atomicAdd(&g_gcnt[g], 1.f);
    }
}
__global__ void k_finalize() {
    int g = threadIdx.x;
    if (g < Gg) {
        float denom = fmaxf(g_gcnt[g] * (float)Dd, 1.f);
        float mean = g_gsum[g] / denom;
        float var = g_gsq[g] / denom - mean * mean;
        g_gmean[g] = mean;
        g_grstd[g] = rsqrtf(var + EPSv);
    }
}
__global__ void k_apply(const int* __restrict__ batch,
                        const float* __restrict__ lnw, const float* __restrict__ lnb,
                        float* __restrict__ out) {
    int i = blockIdx.x * blockDim.x + threadIdx.x;
    if (i >= Nn * 75) return;
    int n = i / 75, d0 = (i - n * 75) * 4;
    int g = __ldg(&batch[n]);
    float mean = g_gmean[g], rstd = g_grstd[g];
    float4 x = *(const float4*)&g_xenc[(size_t)n * Dd + d0];
    float4 wv = __ldg((const float4*)&lnw[d0]);
    float4 bv = __ldg((const float4*)&lnb[d0]);
    float4 o;
    o.x = (x.x - mean) * rstd * wv.x + bv.x;
    o.y = (x.y - mean) * rstd * wv.y + bv.y;
    o.z = (x.z - mean) * rstd * wv.z + bv.z;
    o.w = (x.w - mean) * rstd * wv.w + bv.w;
    *(float4*)&out[(size_t)n * Dd + d0] = o;
}

// ---------------- launch ---------------------------------------------------------
static float* symf(const void* s) {
    void* p = nullptr;
    cudaGetSymbolAddress(&p, s);
    return (float*)p;
}

extern "C" void kernel_launch(void* const* d_in, const int* in_sizes, int n_in,
                              void* d_out, int out_size) {
    const int*   x_tok  = (const int*)d_in[0];
    const int*   ea_tok = (const int*)d_in[1];
    const int*   eidx   = (const int*)d_in[2];
    const int*   ase    = (const int*)d_in[3];
    const int*   batch  = (const int*)d_in[4];
    const float* emb    = (const float*)d_in[5];
    const float* ew1  = (const float*)d_in[6];
    const float* eb1  = (const float*)d_in[7];
    const float* ew2  = (const float*)d_in[8];
    const float* eb2  = (const float*)d_in[9];
    const float* n1w1 = (const float*)d_in[10];
    const float* n1b1 = (const float*)d_in[11];
    const float* n1w2 = (const float*)d_in[12];
    const float* n1b2 = (const float*)d_in[13];
    const float* n2w1 = (const float*)d_in[14];
    const float* n2b1 = (const float*)d_in[15];
    const float* n2w2 = (const float*)d_in[16];
    const float* n2b2 = (const float*)d_in[17];
    const float* lnw  = (const float*)d_in[18];
    const float* lnb  = (const float*)d_in[19];

    const int* row = eidx;
    const int* col = eidx + Ee;

    float* out = (float*)d_out;
    float* edge_out = out + (size_t)Nn * Dd;

    float* pembA = symf(g_embA); float* pembB = symf(g_embB);
    float* pembC = symf(g_embC); float* pembD = symf(g_embD);
    float* pembF = symf(g_embF);
    float* pgsA  = symf(g_gsA);  float* pgsB  = symf(g_gsB);
    float* pgsD  = symf(g_gsD);  float* pgsF  = symf(g_gsF);
    float* ph    = symf(g_h);
    float* pagg  = symf(g_agg);  float* pxenc = symf(g_xenc);
    float* pw2p  = symf(g_w2p);  float* pw12  = symf(g_w12);
    float* pwcat = symf(g_wcat); float* pbcat = symf(g_bcat);
    float* pb2   = symf(g_b2);   float* pbb   = symf(g_bb);
    float* pcnt  = symf(g_cnt);

    const int T256 = 256;
    dim3 gV(5, (Vv + BMt - 1) / BMt);
    dim3 gW(5, (Dd + BMt - 1) / BMt);
    dim3 gE(10, (Ee + BMt - 1) / BMt);
    dim3 gN(5, (Nn + BMt - 1) / BMt);

    // [0] init  [1] sign/cnt
    k_init<<<2048, T256>>>();
    k_signset_cnt<<<(Ee + T256 - 1) / T256, T256>>>(ase, col);
    // [2..4] embA/embB/embC
    k_gemm_tc<0><<<gV, T256>>>(Vv, Dd, emb, nullptr, ew1,           Dd, nullptr, nullptr, pembA, nullptr, nullptr, nullptr, nullptr, nullptr);
    k_gemm_tc<0><<<gV, T256>>>(Vv, Dd, emb, nullptr, ew1 + 300*300, Dd, nullptr, nullptr, pembB, nullptr, nullptr, nullptr, nullptr, nullptr);
    k_gemm_tc<0><<<gV, T256>>>(Vv, Dd, emb, nullptr, ew1 + 600*300, Dd, nullptr, nullptr, pembC, nullptr, nullptr, nullptr, nullptr, nullptr);
    // [5] PROFILE PROBE: small dual-GEMM on stale data into scratch (g_xenc,
    //     fully overwritten by node2-l2 below; final output unaffected).
    k_gemm_tc<3><<<dim3(10, 100), T256>>>(12800, 2 * Dd, ph, nullptr, pwcat, 2 * Dd, pbcat, nullptr,
                                          pxenc, pxenc, pgsD, row, col, nullptr);
    // [6..] remaining precompute
    k_gemm_tc<0><<<gV, T256>>>(Vv, Dd, emb, nullptr, n1w1,          Dd, nullptr, nullptr, pembD, nullptr, nullptr, nullptr, nullptr, nullptr);
    k_gemm_tc<0><<<gV, T256>>>(Vv, Dd, emb, nullptr, n2w1,          Dd, nullptr, nullptr, pembF, nullptr, nullptr, nullptr, nullptr, nullptr);
    k_gemm_tc<0><<<gW, T256>>>(Dd, Dd, ew2,  nullptr, n1w1 + 300*300, Dd, nullptr, nullptr, pw2p, nullptr, nullptr, nullptr, nullptr, nullptr);
    k_gemm_tc<0><<<gW, T256>>>(Dd, Dd, n1w2, nullptr, n2w1 + 300*300, Dd, nullptr, nullptr, pw12, nullptr, nullptr, nullptr, nullptr, nullptr);
    k_vecmat<<<3, 128>>>(pb2, eb2,  n1w1 + 300*300, n1b1);
    k_vecmat<<<3, 128>>>(pbb, n1b2, n2w1 + 300*300, nullptr);
    k_build_wcat<<<(Dd * 2 * Dd + T256 - 1) / T256, T256>>>(ew2, eb2);

    // gather-sums + edge layer-1
    int gsGrid = (Nn * 75 + T256 - 1) / T256;
    k_gsum2<<<gsGrid, T256>>>(x_tok, pembA, pembB, pgsA, pgsB);
    k_gsum2<<<gsGrid, T256>>>(x_tok, pembD, pembF, pgsD, pgsF);
    k_edge_l1<<<(Ee * 75 + T256 - 1) / T256, T256>>>(ea_tok, row, col, eb1);

    // dual GEMM: edge_enc (store) + h2 (relu + gsD[row]) scattered into aggsum
    k_gemm_tc<3><<<gE, T256>>>(Ee, 2 * Dd, ph, nullptr, pwcat, 2 * Dd, pbcat, nullptr,
                               edge_out, pagg, pgsD, row, col, nullptr);

    // node2 layer-1: hidden = relu(aggsum@W12/cnt + gsF + (cnt>0)bb + n2b1)
    k_gemm_tc<5><<<gN, T256>>>(Nn, Dd, pagg, nullptr, pw12, Dd, n2b1, pbb,
                               ph, nullptr, pgsF, nullptr, nullptr, pcnt);
    // node2 layer-2
    k_gemm_tc<0><<<gN, T256>>>(Nn, Dd, ph, nullptr, n2w2, Dd, n2b2, nullptr,
                               pxenc, nullptr, nullptr, nullptr, nullptr, nullptr);

    // graph layer norm
    k_stats<<<Nn, 128>>>(batch);
    k_finalize<<<1, 128>>>();
    k_apply<<<(Nn * 75 + T256 - 1) / T256, T256>>>(batch, lnw, lnb, out);
}